// round 13
// baseline (speedup 1.0000x reference)
#include <cuda_runtime.h>
#include <cuda_bf16.h>
#include <math.h>
#include <cstdint>

#define Tn 1024
#define Hn 2048
#define In 1408
#define IGU 2816            // 2*In (gate||up concat)
#define En 64
#define Fn 8
#define Kn 8
#define Rn 8
#define ISHn 2816
#define SH2 5632            // 2*ISHn
#define TOPKn 6
#define KRn 64

// ---------------- scratch (device globals; allocation-free) ----------------
__device__ float g_soft[Tn * Fn * Kn];
__device__ float g_scalar[Tn * Fn];
__device__ int   g_cnt[Fn];
__device__ int   g_tok[Fn * Tn];
__device__ int   g_pos[Fn * Tn];
__device__ float g_xe[(size_t)Fn * Tn * Hn];
__device__ float g_gu[(size_t)Fn * Tn * IGU];      // gate||up outputs
__device__ float g_mgu[(size_t)Fn * Tn * 128];     // LoRA-a gate||up (rounded)
__device__ float g_hmid[(size_t)Fn * Tn * In];
__device__ float g_md[(size_t)Fn * Tn * KRn];
__device__ float g_down[(size_t)Fn * Tn * Hn];
__device__ float g_qbtgu[(size_t)Fn * IGU * 128];  // block-diag, pre-rounded
__device__ float g_qbtd[(size_t)Fn * Hn * KRn];    // pre-rounded
__device__ float g_shgu[(size_t)Tn * SH2];
__device__ float g_shm[(size_t)Tn * ISHn];
__device__ float g_sgu[Fn * IGU];                  // gate_scale||up_scale (fp32)
__device__ float g_xr[(size_t)Tn * Hn];            // rounded x (shared path A)

// ---------------- helpers ----------------
__device__ __forceinline__ float tf32r(float x) {
    float y;
    asm("cvt.rna.tf32.f32 %0, %1;" : "=f"(y) : "f"(x));
    return y;
}
__device__ __forceinline__ uint32_t smem_u32(const void* p) {
    uint32_t a;
    asm("{ .reg .u64 t; cvta.to.shared.u64 t, %1; cvt.u32.u64 %0, t; }" : "=r"(a) : "l"(p));
    return a;
}
__device__ __forceinline__ void cpa16(uint32_t dst, const void* src, bool pred) {
    int sz = pred ? 16 : 0;
    asm volatile("cp.async.cg.shared.global [%0], [%1], 16, %2;"
                 :: "r"(dst), "l"(src), "r"(sz) : "memory");
}
#define CP_COMMIT() asm volatile("cp.async.commit_group;" ::: "memory")
#define CP_WAIT1() asm volatile("cp.async.wait_group 1;" ::: "memory")

#define MMA_TF32(d, a, b)                                                      \
    asm volatile(                                                              \
        "mma.sync.aligned.m16n8k8.row.col.f32.tf32.tf32.f32 "                  \
        "{%0,%1,%2,%3}, {%4,%5,%6,%7}, {%8,%9}, {%0,%1,%2,%3};\n"              \
        : "+f"((d)[0]), "+f"((d)[1]), "+f"((d)[2]), "+f"((d)[3])               \
        : "r"(__float_as_uint((a)[0])), "r"(__float_as_uint((a)[1])),          \
          "r"(__float_as_uint((a)[2])), "r"(__float_as_uint((a)[3])),          \
          "r"(__float_as_uint((b)[0])), "r"(__float_as_uint((b)[1])))

// ---------------- rounding copy (fp32 -> tf32 RNA), for x only ----------------
__global__ void round_copy(const float4* __restrict__ in, float4* __restrict__ out, int n4) {
    int i = blockIdx.x * blockDim.x + threadIdx.x;
    if (i >= n4) return;
    float4 v = in[i];
    v.x = tf32r(v.x); v.y = tf32r(v.y); v.z = tf32r(v.z); v.w = tf32r(v.w);
    out[i] = v;
}

// ---------------- router (exact fp32: top-k must not flip) ----------------
__global__ void router_kernel(const float* __restrict__ x,
                              const float* __restrict__ gw,
                              const int* __restrict__ inv,
                              float* __restrict__ soft,
                              float* __restrict__ scal) {
    __shared__ float xs[Hn];
    __shared__ float sc[En];
    const int t = blockIdx.x;
    const int tid = threadIdx.x;  // 128 threads
    const float4* xv = reinterpret_cast<const float4*>(x + (size_t)t * Hn);
    for (int i = tid; i < Hn / 4; i += 128)
        reinterpret_cast<float4*>(xs)[i] = xv[i];
    __syncthreads();
    const int lane = tid & 31, w = tid >> 5;
    for (int e = w; e < En; e += 4) {
        const float* g = gw + (size_t)e * Hn;
        float s = 0.f;
        for (int h = lane; h < Hn; h += 32) s += xs[h] * g[h];
#pragma unroll
        for (int o = 16; o; o >>= 1) s += __shfl_xor_sync(0xffffffffu, s, o);
        if (lane == 0) sc[e] = s;
    }
    __syncthreads();
    if (tid == 0) {
        float mx = -1e30f;
        for (int e = 0; e < En; e++) mx = fmaxf(mx, sc[e]);
        float p[En];
        float sum = 0.f;
        for (int e = 0; e < En; e++) { p[e] = expf(sc[e] - mx); sum += p[e]; }
        float is = 1.f / sum;
        for (int e = 0; e < En; e++) p[e] *= is;
        float wv[En];
        for (int e = 0; e < En; e++) wv[e] = 0.f;
        for (int j = 0; j < TOPKn; j++) {
            int best = 0;
            float bv = -1.f;
            for (int e = 0; e < En; e++) {
                if (wv[e] == 0.f && p[e] > bv) { bv = p[e]; best = e; }
            }
            wv[best] = p[best];
        }
        for (int f = 0; f < Fn; f++) {
            float fl[Kn];
            float ssum = 0.f, fmx = -1e30f;
            for (int k = 0; k < Kn; k++) {
                int e = inv[f * Kn + k];
                float v = wv[e];
                ssum += v;
                float l = (v == 0.f) ? -1e9f : v;
                fl[k] = l;
                fmx = fmaxf(fmx, l);
            }
            float es = 0.f, ex[Kn];
            for (int k = 0; k < Kn; k++) { ex[k] = expf(fl[k] - fmx); es += ex[k]; }
            float ies = 1.f / es;
            for (int k = 0; k < Kn; k++)
                soft[((size_t)t * Fn + f) * Kn + k] = ex[k] * ies;
            scal[(size_t)t * Fn + f] = ssum;
        }
    }
}

// ---------------- deterministic per-group token compaction ----------------
__global__ void compact_kernel(const float* __restrict__ scal,
                               int* __restrict__ cnt,
                               int* __restrict__ tok,
                               int* __restrict__ pos) {
    const int z = blockIdx.x;
    const int t = threadIdx.x;  // Tn threads
    __shared__ int sbuf[Tn];
    int active = (scal[(size_t)t * Fn + z] != 0.f) ? 1 : 0;
    sbuf[t] = active;
    __syncthreads();
    for (int off = 1; off < Tn; off <<= 1) {
        int v = (t >= off) ? sbuf[t - off] : 0;
        __syncthreads();
        sbuf[t] += v;
        __syncthreads();
    }
    int incl = sbuf[t];
    if (active) {
        tok[z * Tn + incl - 1] = t;
        pos[z * Tn + t] = incl - 1;
    } else {
        pos[z * Tn + t] = -1;
    }
    if (t == Tn - 1) cnt[z] = incl;
}

// ---------------- xe (compacted, tf32-rounded at write) ----------------
__global__ void xe_kernel(const float* __restrict__ x,
                          const float* __restrict__ muW,
                          const float* __restrict__ soft,
                          const int* __restrict__ cnt,
                          const int* __restrict__ tok,
                          float* __restrict__ xe) {
    size_t idx = (size_t)blockIdx.x * blockDim.x + threadIdx.x;
    if (idx >= (size_t)Fn * Tn * Hn) return;
    int z = (int)(idx / ((size_t)Tn * Hn));
    int rem = (int)(idx % ((size_t)Tn * Hn));
    int i = rem / Hn, h = rem % Hn;
    if (i >= cnt[z]) return;
    int t = tok[z * Tn + i];
    const float* mw = muW + ((size_t)z * Hn + h) * Kn;
    const float* sf = soft + ((size_t)t * Fn + z) * Kn;
    float s = x[(size_t)t * Hn + h];
#pragma unroll
    for (int k = 0; k < Kn; k++) s += sf[k] * mw[k];
    xe[idx] = tf32r(s);
}

// ---------------- qbt builders (pre-rounded; B-cvt is idempotent) ----------
__global__ void tq2_kernel(const float* __restrict__ gqb, const float* __restrict__ uqb,
                           float* __restrict__ outp) {
    int total = Fn * IGU * 128;
    int idx = blockIdx.x * blockDim.x + threadIdx.x;
    if (idx >= total) return;
    int z = idx / (IGU * 128);
    int rem = idx % (IGU * 128);
    int n = rem >> 7, kr = rem & 127;
    float v = 0.f;
    if (n < In) {
        if (kr < 64) {
            int k = kr >> 3, r = kr & 7;
            v = tf32r(gqb[(((size_t)z * Kn + k) * In + n) * Rn + r]);
        }
    } else {
        if (kr >= 64) {
            int k = (kr - 64) >> 3, r = kr & 7;
            v = tf32r(uqb[(((size_t)z * Kn + k) * In + (n - In)) * Rn + r]);
        }
    }
    outp[idx] = v;
}
__global__ void tq_kernel(const float* __restrict__ qb, float* __restrict__ outp, int Nd) {
    int total = Fn * Nd * KRn;
    int idx = blockIdx.x * blockDim.x + threadIdx.x;
    if (idx >= total) return;
    int z = idx / (Nd * KRn);
    int rem = idx % (Nd * KRn);
    int n = rem >> 6, kr = rem & 63;
    int k = kr >> 3, r = kr & 7;
    outp[idx] = tf32r(qb[(((size_t)z * Kn + k) * Nd + n) * Rn + r]);
}

// ---------------- scale concat (fp32) ----------------
__global__ void sc2(const float* __restrict__ gs, const float* __restrict__ us,
                    float* __restrict__ sgu) {
    int i = blockIdx.x * blockDim.x + threadIdx.x;
    if (i >= 2 * Fn * In) return;
    int seg = i >= Fn * In;
    int j = i - seg * Fn * In;
    int z = j / In, r = j % In;
    sgu[z * IGU + seg * In + r] = (seg ? us : gs)[j];
}

// ---------------- hmid = silu(gate)*up (rounded) ----------------
__global__ void fuse_kernel(const float* __restrict__ gu,
                            const int* __restrict__ cnt,
                            float* __restrict__ hm) {
    size_t idx = (size_t)blockIdx.x * blockDim.x + threadIdx.x;
    if (idx >= (size_t)Fn * Tn * In) return;
    int z = (int)(idx / ((size_t)Tn * In));
    int rem = (int)(idx % ((size_t)Tn * In));
    int i = rem / In, c = rem % In;
    if (i >= cnt[z]) return;
    size_t base = ((size_t)z * Tn + i) * IGU;
    float g = gu[base + c], u = gu[base + In + c];
    hm[idx] = tf32r(g / (1.f + expf(-g)) * u);
}

__global__ void swiglu_kernel(const float* __restrict__ sgu, float* __restrict__ hm) {
    size_t idx = (size_t)blockIdx.x * blockDim.x + threadIdx.x;
    if (idx >= (size_t)Tn * ISHn) return;
    int t = (int)(idx / ISHn), c = (int)(idx % ISHn);
    size_t base = (size_t)t * SH2;
    float g = sgu[base + c], u = sgu[base + ISHn + c];
    hm[idx] = tf32r(g / (1.f + expf(-g)) * u);
}

// ---------------- out[t] += sum_z active: down[z][pos[z,t]] ----------------
__global__ void reduce_kernel(float* __restrict__ out, const float* __restrict__ down,
                              const int* __restrict__ pos) {
    int idx = blockIdx.x * blockDim.x + threadIdx.x;
    if (idx >= Tn * Hn) return;
    int t = idx / Hn, h = idx % Hn;
    float s = out[idx];
#pragma unroll
    for (int z = 0; z < Fn; z++) {
        int p = pos[z * Tn + t];
        if (p >= 0) s += down[((size_t)z * Tn + p) * Hn + h];
    }
    out[idx] = s;
}

// ---------------- cp.async tf32 GEMM body, tile 128x128 ----------------
// C[MxN] = A[MxK] * rna(Bcat)[NxK]^T. A pre-rounded by producers; B fragments
// rounded in-register. Bcat = B rows [0,nsplit) || B2 rows.
// MODE 0: C=acc
// MODE 1: C=tf32r(acc*soft[tok[r], z, (n&63)>>3])
// MODE 2: C=C + colscale[n]*acc
// MODE 5: C=rowscal[tok[r]*Fn+z]*(C + colscale[n]*acc)
#define KC 32
#define SM_LD 36
#define SM_BUF (128 * SM_LD)
#define STAGE_FLOATS (2 * SM_BUF)
#define SMEM_BYTES (3 * STAGE_FLOATS * 4)

struct GArgs {
    const float* A; int lda; size_t sA;
    const float* B; int ldb; size_t sB;
    const float* B2; int nsplit;
    float* C; int ldc; size_t sC;
    int N, Ktot;
    const float* soft;
    const float* rowscal;
    const float* colscale; size_t sCs;
    const int* cntp;
    const int* tokp;
};

template <int MODE>
__device__ void gemm_body(const GArgs& g, int bxi, int byi, int z) {
    const int Mz = g.cntp ? g.cntp[z] : Tn;
    const int bm = byi * 128, bn = bxi * 128;
    if (bm >= Mz) return;
    const float* A = g.A + (size_t)z * g.sA;
    const float* B = g.B + (size_t)z * g.sB;
    const float* B2 = g.B2 + (size_t)z * g.sB;
    float* C = g.C + (size_t)z * g.sC;
    const int lda = g.lda, ldb = g.ldb, ldc = g.ldc, N = g.N, nsplit = g.nsplit;
    const float* cs = (MODE == 2 || MODE == 5) ? g.colscale + (size_t)z * g.sCs : nullptr;
    const int* tk = (MODE == 1 || MODE == 5) ? g.tokp + z * Tn : nullptr;

    extern __shared__ float smf[];
    const uint32_t sbase = smem_u32(smf);
    const int tid = threadIdx.x, lane = tid & 31, wid = tid >> 5;
    const int wm = (wid >> 2) * 64, wn = (wid & 3) * 32;

    int arow[4], kq4[4];
#pragma unroll
    for (int i = 0; i < 4; i++) {
        int lin = tid + i * 256;
        arow[i] = lin >> 3;
        kq4[i] = (lin & 7) << 2;
    }
    float acc[4][4][4];
#pragma unroll
    for (int a = 0; a < 4; a++)
#pragma unroll
        for (int b = 0; b < 4; b++)
#pragma unroll
            for (int c = 0; c < 4; c++) acc[a][b][c] = 0.f;

    auto issue = [&](int kt, int s) {
        const int k0 = kt * KC;
#pragma unroll
        for (int i = 0; i < 4; i++) {
            uint32_t da = sbase + (uint32_t)((s * STAGE_FLOATS + arow[i] * SM_LD + kq4[i]) * 4);
            cpa16(da, A + (size_t)(bm + arow[i]) * lda + k0 + kq4[i], bm + arow[i] < Mz);
            uint32_t db = da + (uint32_t)(SM_BUF * 4);
            int n = bn + arow[i];
            const float* bs = (n < nsplit) ? B + (size_t)n * ldb
                                           : B2 + (size_t)(n - nsplit) * ldb;
            cpa16(db, bs + k0 + kq4[i], n < N);
        }
    };

    const int KT = g.Ktot / KC;
    issue(0, 0);
    CP_COMMIT();
    if (KT > 1) issue(1, 1);
    CP_COMMIT();

    for (int kt = 0; kt < KT; kt++) {
        CP_WAIT1();
        __syncthreads();
        if (kt + 2 < KT) issue(kt + 2, (kt + 2) % 3);
        CP_COMMIT();
        const float* Ab = smf + (kt % 3) * STAGE_FLOATS;
        const float* Bb = Ab + SM_BUF;
#pragma unroll
        for (int ks = 0; ks < 4; ks++) {
            int kk = ks * 8 + (lane & 3);
            float a[4][4], b[4][2];
#pragma unroll
            for (int mi = 0; mi < 4; mi++) {
                const float* p = Ab + (wm + mi * 16 + (lane >> 2)) * SM_LD + kk;
                a[mi][0] = p[0];
                a[mi][1] = p[8 * SM_LD];
                a[mi][2] = p[4];
                a[mi][3] = p[8 * SM_LD + 4];
            }
#pragma unroll
            for (int ni = 0; ni < 4; ni++) {
                const float* q = Bb + (wn + ni * 8 + (lane >> 2)) * SM_LD + kk;
                b[ni][0] = tf32r(q[0]);
                b[ni][1] = tf32r(q[4]);
            }
#pragma unroll
            for (int mi = 0; mi < 4; mi++)
#pragma unroll
                for (int ni = 0; ni < 4; ni++) MMA_TF32(acc[mi][ni], a[mi], b[ni]);
        }
    }

    // epilogue
#pragma unroll
    for (int mi = 0; mi < 4; mi++) {
#pragma unroll
        for (int ni = 0; ni < 4; ni++) {
            int cb = bn + wn + ni * 8;
            if (cb >= N) continue;
            int c = cb + ((lane & 3) << 1);
#pragma unroll
            for (int hh = 0; hh < 2; hh++) {
                int r = bm + wm + mi * 16 + (lane >> 2) + hh * 8;
                if (r >= Mz) continue;
                float v0 = acc[mi][ni][hh * 2 + 0];
                float v1 = acc[mi][ni][hh * 2 + 1];
                size_t off = (size_t)r * ldc + c;
                if (MODE == 1) {
                    float s = g.soft[((size_t)tk[r] * Fn + z) * Kn + ((c & 63) >> 3)];
                    v0 = tf32r(v0 * s);
                    v1 = tf32r(v1 * s);
                } else if (MODE == 2) {
                    float2 prev = *reinterpret_cast<const float2*>(&C[off]);
                    v0 = prev.x + cs[c] * v0;
                    v1 = prev.y + cs[c + 1] * v1;
                } else if (MODE == 5) {
                    float rs = g.rowscal[(size_t)tk[r] * Fn + z];
                    float2 prev = *reinterpret_cast<const float2*>(&C[off]);
                    v0 = rs * (prev.x + cs[c] * v0);
                    v1 = rs * (prev.y + cs[c + 1] * v1);
                }
                *reinterpret_cast<float2*>(&C[off]) = make_float2(v0, v1);
            }
        }
    }
}

// dual-GEMM kernel: linear grid; first nb1 blocks run GEMM1 (small, wave-1),
// the rest run GEMM2. Decode x-fastest to match the 3D grid ordering.
template <int M1, int M2>
__global__ void __launch_bounds__(256, 2)
gemm_dual(GArgs g1, int gx1, int gy1, int nb1, GArgs g2, int gx2, int gy2) {
    int b = blockIdx.x;
    if (b < nb1) {
        int z = b / (gx1 * gy1);
        int rem = b % (gx1 * gy1);
        gemm_body<M1>(g1, rem % gx1, rem / gx1, z);
    } else {
        b -= nb1;
        int z = b / (gx2 * gy2);
        int rem = b % (gx2 * gy2);
        gemm_body<M2>(g2, rem % gx2, rem / gx2, z);
    }
}

// ---------------- host ----------------
#define SYMP(v, T) ({ void* _p = nullptr; cudaGetSymbolAddress(&_p, v); (T*)_p; })

extern "C" void kernel_launch(void* const* d_in, const int* in_sizes, int n_in,
                              void* d_out, int out_size) {
    const float* x          = (const float*)d_in[0];
    const float* gate_wt    = (const float*)d_in[1];
    const int*   inv        = (const int*)d_in[2];
    const float* mask_up_W  = (const float*)d_in[3];
    const float* gate_W     = (const float*)d_in[4];
    const float* gate_qa    = (const float*)d_in[5];
    const float* gate_qb    = (const float*)d_in[6];
    const float* gate_scale = (const float*)d_in[7];
    const float* up_W       = (const float*)d_in[8];
    const float* up_qa      = (const float*)d_in[9];
    const float* up_qb      = (const float*)d_in[10];
    const float* up_scale   = (const float*)d_in[11];
    const float* down_W     = (const float*)d_in[12];
    const float* down_qa    = (const float*)d_in[13];
    const float* down_qb    = (const float*)d_in[14];
    const float* down_scale = (const float*)d_in[15];
    const float* sh_gate_W  = (const float*)d_in[16];
    const float* sh_up_W    = (const float*)d_in[17];
    const float* sh_down_W  = (const float*)d_in[18];
    float* out = (float*)d_out;

    float* p_soft  = SYMP(g_soft, float);
    float* p_scal  = SYMP(g_scalar, float);
    int*   p_cnt   = SYMP(g_cnt, int);
    int*   p_tok   = SYMP(g_tok, int);
    int*   p_pos   = SYMP(g_pos, int);
    float* p_xe    = SYMP(g_xe, float);
    float* p_gu    = SYMP(g_gu, float);
    float* p_mgu   = SYMP(g_mgu, float);
    float* p_hmid  = SYMP(g_hmid, float);
    float* p_md    = SYMP(g_md, float);
    float* p_down  = SYMP(g_down, float);
    float* p_qbtgu = SYMP(g_qbtgu, float);
    float* p_qbtd  = SYMP(g_qbtd, float);
    float* p_shgu  = SYMP(g_shgu, float);
    float* p_shm   = SYMP(g_shm, float);
    float* p_sgu   = SYMP(g_sgu, float);
    float* p_xr    = SYMP(g_xr, float);

    cudaFuncSetAttribute(gemm_dual<1, 0>, cudaFuncAttributeMaxDynamicSharedMemorySize, SMEM_BYTES);
    cudaFuncSetAttribute(gemm_dual<1, 0>, cudaFuncAttributePreferredSharedMemoryCarveout, 100);
    cudaFuncSetAttribute(gemm_dual<0, 2>, cudaFuncAttributeMaxDynamicSharedMemorySize, SMEM_BYTES);
    cudaFuncSetAttribute(gemm_dual<0, 2>, cudaFuncAttributePreferredSharedMemoryCarveout, 100);
    cudaFuncSetAttribute(gemm_dual<0, 5>, cudaFuncAttributeMaxDynamicSharedMemorySize, SMEM_BYTES);
    cudaFuncSetAttribute(gemm_dual<0, 5>, cudaFuncAttributePreferredSharedMemoryCarveout, 100);

#define NB(n) ((int)(((n) + 255) / 256))

    // 1. router (exact fp32)
    router_kernel<<<Tn, 128>>>(x, gate_wt, inv, p_soft, p_scal);
    // 2. deterministic token compaction
    compact_kernel<<<Fn, Tn>>>(p_scal, p_cnt, p_tok, p_pos);
    // 3. xe (compacted, rounded at producer)
    xe_kernel<<<NB((size_t)Fn * Tn * Hn), 256>>>(x, mask_up_W, p_soft, p_cnt, p_tok, p_xe);
    // 4. rounded x for shared path (independent)
    round_copy<<<NB((size_t)Tn * Hn / 4), 256>>>(
        (const float4*)x, (float4*)p_xr, (int)((size_t)Tn * Hn / 4));
    // 5-7. weight layout preps (independent of GEMMs below until consumed)
    tq2_kernel<<<NB(Fn * IGU * 128), 256>>>(gate_qb, up_qb, p_qbtgu);
    tq_kernel<<<NB(Fn * Hn * KRn), 256>>>(down_qb, p_qbtd, Hn);
    sc2<<<NB(2 * Fn * In), 256>>>(gate_scale, up_scale, p_sgu);

    // arg structs
    GArgs aGU  = { p_xe, Hn, (size_t)Tn * Hn, gate_W, Hn, (size_t)In * Hn, up_W, In,
                   p_gu, IGU, (size_t)Tn * IGU, IGU, Hn,
                   nullptr, nullptr, nullptr, 0, p_cnt, nullptr };
    GArgs aLA  = { p_xe, Hn, (size_t)Tn * Hn, gate_qa, Hn, (size_t)KRn * Hn, up_qa, KRn,
                   p_mgu, 128, (size_t)Tn * 128, 128, Hn,
                   p_soft, nullptr, nullptr, 0, p_cnt, p_tok };
    GArgs aMIX = { p_mgu, 128, (size_t)Tn * 128, p_qbtgu, 128, (size_t)IGU * 128, p_qbtgu, IGU,
                   p_gu, IGU, (size_t)Tn * IGU, IGU, 128,
                   nullptr, nullptr, p_sgu, IGU, p_cnt, nullptr };
    GArgs aSHG = { p_xr, Hn, 0, sh_gate_W, Hn, 0, sh_up_W, ISHn,
                   p_shgu, SH2, 0, SH2, Hn,
                   nullptr, nullptr, nullptr, 0, nullptr, nullptr };
    GArgs aDLA = { p_hmid, In, (size_t)Tn * In, down_qa, In, (size_t)KRn * In, down_qa, KRn,
                   p_md, KRn, (size_t)Tn * KRn, KRn, In,
                   p_soft, nullptr, nullptr, 0, p_cnt, p_tok };
    GArgs aDW0 = { p_hmid, In, (size_t)Tn * In, down_W, In, (size_t)Hn * In, down_W, Hn,
                   p_down, Hn, (size_t)Tn * Hn, Hn, In,
                   nullptr, nullptr, nullptr, 0, p_cnt, nullptr };
    GArgs aSHD = { p_shm, ISHn, 0, sh_down_W, ISHn, 0, sh_down_W, Hn,
                   out, Hn, 0, Hn, ISHn,
                   nullptr, nullptr, nullptr, 0, nullptr, nullptr };
    GArgs aFIN = { p_md, KRn, (size_t)Tn * KRn, p_qbtd, KRn, (size_t)Hn * KRn, p_qbtd, Hn,
                   p_down, Hn, (size_t)Tn * Hn, Hn, KRn,
                   nullptr, p_scal, down_scale, Hn, p_cnt, p_tok };

    // 8. DUAL: LoRA-a (64 blocks first) + gate||up GEMM (1408)
    gemm_dual<1, 0><<<64 + 1408, 256, SMEM_BYTES>>>(aLA, 1, 8, 64, aGU, 22, 8);

    // 9. DUAL: shared gate||up (352 first) + mix GEMM in-place (1408)
    gemm_dual<0, 2><<<352 + 1408, 256, SMEM_BYTES>>>(aSHG, 44, 8, 352, aMIX, 22, 8);

    // 10. hmid = silu(gate)*up
    fuse_kernel<<<NB((size_t)Fn * Tn * In), 256>>>(p_gu, p_cnt, p_hmid);
    // 11. swiglu (shared path; p_shgu ready)
    swiglu_kernel<<<NB((size_t)Tn * ISHn), 256>>>(p_shgu, p_shm);

    // 12. DUAL: down LoRA-a (64 first) + down main GEMM MODE0 (1024)
    gemm_dual<1, 0><<<64 + 1024, 256, SMEM_BYTES>>>(aDLA, 1, 8, 64, aDW0, 16, 8);

    // 13. DUAL: shared down GEMM (128 first) + final down mix MODE5 (1024, K=64)
    gemm_dual<0, 5><<<128 + 1024, 256, SMEM_BYTES>>>(aSHD, 16, 8, 128, aFIN, 16, 8);

    // 14. out += gathered expert outputs
    reduce_kernel<<<NB(Tn * Hn), 256>>>(out, p_down, p_pos);

#undef NB
    (void)in_sizes; (void)n_in; (void)out_size;
}

// round 14
// speedup vs baseline: 1.0303x; 1.0303x over previous
#include <cuda_runtime.h>
#include <cuda_bf16.h>
#include <math.h>
#include <cstdint>

#define Tn 1024
#define Hn 2048
#define In 1408
#define IGU 2816            // 2*In (gate||up concat)
#define En 64
#define Fn 8
#define Kn 8
#define Rn 8
#define ISHn 2816
#define SH2 5632            // 2*ISHn
#define TOPKn 6
#define KRn 64

// ---------------- scratch (device globals; allocation-free) ----------------
__device__ float g_soft[Tn * Fn * Kn];
__device__ float g_scalar[Tn * Fn];
__device__ int   g_cnt[Fn];
__device__ int   g_tok[Fn * Tn];
__device__ int   g_pos[Fn * Tn];
__device__ float g_xe[(size_t)Fn * Tn * Hn];
__device__ float g_gu[(size_t)Fn * Tn * IGU];      // gate||up outputs
__device__ float g_mgu[(size_t)Fn * Tn * 128];     // LoRA-a gate||up (rounded)
__device__ float g_hmid[(size_t)Fn * Tn * In];
__device__ float g_md[(size_t)Fn * Tn * KRn];
__device__ float g_mixd[(size_t)Fn * Tn * Hn];
__device__ float g_down[(size_t)Fn * Tn * Hn];
__device__ float g_qbtgu[(size_t)Fn * IGU * 128];  // block-diag, pre-rounded
__device__ float g_qbtd[(size_t)Fn * Hn * KRn];    // pre-rounded
__device__ float g_shgu[(size_t)Tn * SH2];
__device__ float g_shm[(size_t)Tn * ISHn];
__device__ float g_sgu[Fn * IGU];                  // gate_scale||up_scale (fp32)
__device__ float g_xr[(size_t)Tn * Hn];            // rounded x (shared path A)

// ---------------- helpers ----------------
__device__ __forceinline__ float tf32r(float x) {
    float y;
    asm("cvt.rna.tf32.f32 %0, %1;" : "=f"(y) : "f"(x));
    return y;
}
__device__ __forceinline__ uint32_t smem_u32(const void* p) {
    uint32_t a;
    asm("{ .reg .u64 t; cvta.to.shared.u64 t, %1; cvt.u32.u64 %0, t; }" : "=r"(a) : "l"(p));
    return a;
}
__device__ __forceinline__ void cpa16(uint32_t dst, const void* src, bool pred) {
    int sz = pred ? 16 : 0;
    asm volatile("cp.async.cg.shared.global [%0], [%1], 16, %2;"
                 :: "r"(dst), "l"(src), "r"(sz) : "memory");
}
#define CP_COMMIT() asm volatile("cp.async.commit_group;" ::: "memory")
#define CP_WAIT1() asm volatile("cp.async.wait_group 1;" ::: "memory")

#define MMA_TF32(d, a, b)                                                      \
    asm volatile(                                                              \
        "mma.sync.aligned.m16n8k8.row.col.f32.tf32.tf32.f32 "                  \
        "{%0,%1,%2,%3}, {%4,%5,%6,%7}, {%8,%9}, {%0,%1,%2,%3};\n"              \
        : "+f"((d)[0]), "+f"((d)[1]), "+f"((d)[2]), "+f"((d)[3])               \
        : "r"(__float_as_uint((a)[0])), "r"(__float_as_uint((a)[1])),          \
          "r"(__float_as_uint((a)[2])), "r"(__float_as_uint((a)[3])),          \
          "r"(__float_as_uint((b)[0])), "r"(__float_as_uint((b)[1])))

// ---------------- rounding copy (fp32 -> tf32 RNA), for x only ----------------
__global__ void round_copy(const float4* __restrict__ in, float4* __restrict__ out, int n4) {
    int i = blockIdx.x * blockDim.x + threadIdx.x;
    if (i >= n4) return;
    float4 v = in[i];
    v.x = tf32r(v.x); v.y = tf32r(v.y); v.z = tf32r(v.z); v.w = tf32r(v.w);
    out[i] = v;
}

// ---------------- router (exact fp32: top-k must not flip) ----------------
__global__ void router_kernel(const float* __restrict__ x,
                              const float* __restrict__ gw,
                              const int* __restrict__ inv,
                              float* __restrict__ soft,
                              float* __restrict__ scal) {
    __shared__ float xs[Hn];
    __shared__ float sc[En];
    const int t = blockIdx.x;
    const int tid = threadIdx.x;  // 128 threads
    const float4* xv = reinterpret_cast<const float4*>(x + (size_t)t * Hn);
    for (int i = tid; i < Hn / 4; i += 128)
        reinterpret_cast<float4*>(xs)[i] = xv[i];
    __syncthreads();
    const int lane = tid & 31, w = tid >> 5;
    for (int e = w; e < En; e += 4) {
        const float* g = gw + (size_t)e * Hn;
        float s = 0.f;
        for (int h = lane; h < Hn; h += 32) s += xs[h] * g[h];
#pragma unroll
        for (int o = 16; o; o >>= 1) s += __shfl_xor_sync(0xffffffffu, s, o);
        if (lane == 0) sc[e] = s;
    }
    __syncthreads();
    if (tid == 0) {
        float mx = -1e30f;
        for (int e = 0; e < En; e++) mx = fmaxf(mx, sc[e]);
        float p[En];
        float sum = 0.f;
        for (int e = 0; e < En; e++) { p[e] = expf(sc[e] - mx); sum += p[e]; }
        float is = 1.f / sum;
        for (int e = 0; e < En; e++) p[e] *= is;
        float wv[En];
        for (int e = 0; e < En; e++) wv[e] = 0.f;
        for (int j = 0; j < TOPKn; j++) {
            int best = 0;
            float bv = -1.f;
            for (int e = 0; e < En; e++) {
                if (wv[e] == 0.f && p[e] > bv) { bv = p[e]; best = e; }
            }
            wv[best] = p[best];
        }
        for (int f = 0; f < Fn; f++) {
            float fl[Kn];
            float ssum = 0.f, fmx = -1e30f;
            for (int k = 0; k < Kn; k++) {
                int e = inv[f * Kn + k];
                float v = wv[e];
                ssum += v;
                float l = (v == 0.f) ? -1e9f : v;
                fl[k] = l;
                fmx = fmaxf(fmx, l);
            }
            float es = 0.f, ex[Kn];
            for (int k = 0; k < Kn; k++) { ex[k] = expf(fl[k] - fmx); es += ex[k]; }
            float ies = 1.f / es;
            for (int k = 0; k < Kn; k++)
                soft[((size_t)t * Fn + f) * Kn + k] = ex[k] * ies;
            scal[(size_t)t * Fn + f] = ssum;
        }
    }
}

// ---------------- deterministic per-group token compaction ----------------
__global__ void compact_kernel(const float* __restrict__ scal,
                               int* __restrict__ cnt,
                               int* __restrict__ tok,
                               int* __restrict__ pos) {
    const int z = blockIdx.x;
    const int t = threadIdx.x;  // Tn threads
    __shared__ int sbuf[Tn];
    int active = (scal[(size_t)t * Fn + z] != 0.f) ? 1 : 0;
    sbuf[t] = active;
    __syncthreads();
    for (int off = 1; off < Tn; off <<= 1) {
        int v = (t >= off) ? sbuf[t - off] : 0;
        __syncthreads();
        sbuf[t] += v;
        __syncthreads();
    }
    int incl = sbuf[t];
    if (active) {
        tok[z * Tn + incl - 1] = t;
        pos[z * Tn + t] = incl - 1;
    } else {
        pos[z * Tn + t] = -1;
    }
    if (t == Tn - 1) cnt[z] = incl;
}

// ---------------- xe (compacted, tf32-rounded at write) ----------------
__global__ void xe_kernel(const float* __restrict__ x,
                          const float* __restrict__ muW,
                          const float* __restrict__ soft,
                          const int* __restrict__ cnt,
                          const int* __restrict__ tok,
                          float* __restrict__ xe) {
    size_t idx = (size_t)blockIdx.x * blockDim.x + threadIdx.x;
    if (idx >= (size_t)Fn * Tn * Hn) return;
    int z = (int)(idx / ((size_t)Tn * Hn));
    int rem = (int)(idx % ((size_t)Tn * Hn));
    int i = rem / Hn, h = rem % Hn;
    if (i >= cnt[z]) return;
    int t = tok[z * Tn + i];
    const float* mw = muW + ((size_t)z * Hn + h) * Kn;
    const float* sf = soft + ((size_t)t * Fn + z) * Kn;
    float s = x[(size_t)t * Hn + h];
#pragma unroll
    for (int k = 0; k < Kn; k++) s += sf[k] * mw[k];
    xe[idx] = tf32r(s);
}

// ---------------- qbt builders (pre-rounded; B-cvt is idempotent) ----------
__global__ void tq2_kernel(const float* __restrict__ gqb, const float* __restrict__ uqb,
                           float* __restrict__ outp) {
    int total = Fn * IGU * 128;
    int idx = blockIdx.x * blockDim.x + threadIdx.x;
    if (idx >= total) return;
    int z = idx / (IGU * 128);
    int rem = idx % (IGU * 128);
    int n = rem >> 7, kr = rem & 127;
    float v = 0.f;
    if (n < In) {
        if (kr < 64) {
            int k = kr >> 3, r = kr & 7;
            v = tf32r(gqb[(((size_t)z * Kn + k) * In + n) * Rn + r]);
        }
    } else {
        if (kr >= 64) {
            int k = (kr - 64) >> 3, r = kr & 7;
            v = tf32r(uqb[(((size_t)z * Kn + k) * In + (n - In)) * Rn + r]);
        }
    }
    outp[idx] = v;
}
__global__ void tq_kernel(const float* __restrict__ qb, float* __restrict__ outp, int Nd) {
    int total = Fn * Nd * KRn;
    int idx = blockIdx.x * blockDim.x + threadIdx.x;
    if (idx >= total) return;
    int z = idx / (Nd * KRn);
    int rem = idx % (Nd * KRn);
    int n = rem >> 6, kr = rem & 63;
    int k = kr >> 3, r = kr & 7;
    outp[idx] = tf32r(qb[(((size_t)z * Kn + k) * Nd + n) * Rn + r]);
}

// ---------------- scale concat (fp32) ----------------
__global__ void sc2(const float* __restrict__ gs, const float* __restrict__ us,
                    float* __restrict__ sgu) {
    int i = blockIdx.x * blockDim.x + threadIdx.x;
    if (i >= 2 * Fn * In) return;
    int seg = i >= Fn * In;
    int j = i - seg * Fn * In;
    int z = j / In, r = j % In;
    sgu[z * IGU + seg * In + r] = (seg ? us : gs)[j];
}

// ---------------- hmid = silu(gate)*up (rounded) ----------------
__global__ void fuse_kernel(const float* __restrict__ gu,
                            const int* __restrict__ cnt,
                            float* __restrict__ hm) {
    size_t idx = (size_t)blockIdx.x * blockDim.x + threadIdx.x;
    if (idx >= (size_t)Fn * Tn * In) return;
    int z = (int)(idx / ((size_t)Tn * In));
    int rem = (int)(idx % ((size_t)Tn * In));
    int i = rem / In, c = rem % In;
    if (i >= cnt[z]) return;
    size_t base = ((size_t)z * Tn + i) * IGU;
    float g = gu[base + c], u = gu[base + In + c];
    hm[idx] = tf32r(g / (1.f + expf(-g)) * u);
}

__global__ void swiglu_kernel(const float* __restrict__ sgu, float* __restrict__ hm) {
    size_t idx = (size_t)blockIdx.x * blockDim.x + threadIdx.x;
    if (idx >= (size_t)Tn * ISHn) return;
    int t = (int)(idx / ISHn), c = (int)(idx % ISHn);
    size_t base = (size_t)t * SH2;
    float g = sgu[base + c], u = sgu[base + ISHn + c];
    hm[idx] = tf32r(g / (1.f + expf(-g)) * u);
}

// ---------------- out[t] += sum_z active: down[z][pos[z,t]] ----------------
__global__ void reduce_kernel(float* __restrict__ out, const float* __restrict__ down,
                              const int* __restrict__ pos) {
    int idx = blockIdx.x * blockDim.x + threadIdx.x;
    if (idx >= Tn * Hn) return;
    int t = idx / Hn, h = idx % Hn;
    float s = out[idx];
#pragma unroll
    for (int z = 0; z < Fn; z++) {
        int p = pos[z * Tn + t];
        if (p >= 0) s += down[((size_t)z * Tn + p) * Hn + h];
    }
    out[idx] = s;
}

// ---------------- cp.async tf32 GEMM body, tile 128x128 ----------------
// C[MxN] = A[MxK] * rna(Bcat)[NxK]^T. A pre-rounded by producers; B fragments
// rounded in-register. Bcat = B rows [0,nsplit) || B2 rows.
// MODE 0: C=acc
// MODE 1: C=tf32r(acc*soft[tok[r], z, (n&63)>>3])
// MODE 2: C=C + colscale[n]*acc
// MODE 3: C=colscale[n]*acc
// MODE 4: C=rowscal[tok[r]*Fn+z]*(acc + mixadd[z,r,n])
// MODE 6: C=C + acc    (split-K accumulate)
#define KC 32
#define SM_LD 36
#define SM_BUF (128 * SM_LD)
#define STAGE_FLOATS (2 * SM_BUF)
#define SMEM_BYTES (3 * STAGE_FLOATS * 4)

struct GArgs {
    const float* A; int lda; size_t sA;
    const float* B; int ldb; size_t sB;
    const float* B2; int nsplit;
    float* C; int ldc; size_t sC;
    int N, Ktot;
    const float* soft;
    const float* rowscal;
    const float* colscale; size_t sCs;
    const float* mixadd;
    const int* cntp;
    const int* tokp;
};

template <int MODE>
__device__ void gemm_body(const GArgs& g, int bxi, int byi, int z) {
    const int Mz = g.cntp ? g.cntp[z] : Tn;
    const int bm = byi * 128, bn = bxi * 128;
    if (bm >= Mz) return;
    const float* A = g.A + (size_t)z * g.sA;
    const float* B = g.B + (size_t)z * g.sB;
    const float* B2 = g.B2 + (size_t)z * g.sB;
    float* C = g.C + (size_t)z * g.sC;
    const int lda = g.lda, ldb = g.ldb, ldc = g.ldc, N = g.N, nsplit = g.nsplit;
    const float* cs = (MODE == 2 || MODE == 3) ? g.colscale + (size_t)z * g.sCs : nullptr;
    const float* mixp = (MODE == 4) ? g.mixadd + (size_t)z * g.sC : nullptr;
    const int* tk = (MODE == 1 || MODE == 4) ? g.tokp + z * Tn : nullptr;

    extern __shared__ float smf[];
    const uint32_t sbase = smem_u32(smf);
    const int tid = threadIdx.x, lane = tid & 31, wid = tid >> 5;
    const int wm = (wid >> 2) * 64, wn = (wid & 3) * 32;

    int arow[4], kq4[4];
#pragma unroll
    for (int i = 0; i < 4; i++) {
        int lin = tid + i * 256;
        arow[i] = lin >> 3;
        kq4[i] = (lin & 7) << 2;
    }
    float acc[4][4][4];
#pragma unroll
    for (int a = 0; a < 4; a++)
#pragma unroll
        for (int b = 0; b < 4; b++)
#pragma unroll
            for (int c = 0; c < 4; c++) acc[a][b][c] = 0.f;

    auto issue = [&](int kt, int s) {
        const int k0 = kt * KC;
#pragma unroll
        for (int i = 0; i < 4; i++) {
            uint32_t da = sbase + (uint32_t)((s * STAGE_FLOATS + arow[i] * SM_LD + kq4[i]) * 4);
            cpa16(da, A + (size_t)(bm + arow[i]) * lda + k0 + kq4[i], bm + arow[i] < Mz);
            uint32_t db = da + (uint32_t)(SM_BUF * 4);
            int n = bn + arow[i];
            const float* bs = (n < nsplit) ? B + (size_t)n * ldb
                                           : B2 + (size_t)(n - nsplit) * ldb;
            cpa16(db, bs + k0 + kq4[i], n < N);
        }
    };

    const int KT = g.Ktot / KC;
    issue(0, 0);
    CP_COMMIT();
    if (KT > 1) issue(1, 1);
    CP_COMMIT();

    for (int kt = 0; kt < KT; kt++) {
        CP_WAIT1();
        __syncthreads();
        if (kt + 2 < KT) issue(kt + 2, (kt + 2) % 3);
        CP_COMMIT();
        const float* Ab = smf + (kt % 3) * STAGE_FLOATS;
        const float* Bb = Ab + SM_BUF;
#pragma unroll
        for (int ks = 0; ks < 4; ks++) {
            int kk = ks * 8 + (lane & 3);
            float a[4][4], b[4][2];
#pragma unroll
            for (int mi = 0; mi < 4; mi++) {
                const float* p = Ab + (wm + mi * 16 + (lane >> 2)) * SM_LD + kk;
                a[mi][0] = p[0];
                a[mi][1] = p[8 * SM_LD];
                a[mi][2] = p[4];
                a[mi][3] = p[8 * SM_LD + 4];
            }
#pragma unroll
            for (int ni = 0; ni < 4; ni++) {
                const float* q = Bb + (wn + ni * 8 + (lane >> 2)) * SM_LD + kk;
                b[ni][0] = tf32r(q[0]);
                b[ni][1] = tf32r(q[4]);
            }
#pragma unroll
            for (int mi = 0; mi < 4; mi++)
#pragma unroll
                for (int ni = 0; ni < 4; ni++) MMA_TF32(acc[mi][ni], a[mi], b[ni]);
        }
    }

    // epilogue
#pragma unroll
    for (int mi = 0; mi < 4; mi++) {
#pragma unroll
        for (int ni = 0; ni < 4; ni++) {
            int cb = bn + wn + ni * 8;
            if (cb >= N) continue;
            int c = cb + ((lane & 3) << 1);
#pragma unroll
            for (int hh = 0; hh < 2; hh++) {
                int r = bm + wm + mi * 16 + (lane >> 2) + hh * 8;
                if (r >= Mz) continue;
                float v0 = acc[mi][ni][hh * 2 + 0];
                float v1 = acc[mi][ni][hh * 2 + 1];
                size_t off = (size_t)r * ldc + c;
                if (MODE == 1) {
                    float s = g.soft[((size_t)tk[r] * Fn + z) * Kn + ((c & 63) >> 3)];
                    v0 = tf32r(v0 * s);
                    v1 = tf32r(v1 * s);
                } else if (MODE == 2) {
                    float2 prev = *reinterpret_cast<const float2*>(&C[off]);
                    v0 = prev.x + cs[c] * v0;
                    v1 = prev.y + cs[c + 1] * v1;
                } else if (MODE == 3) {
                    v0 *= cs[c];
                    v1 *= cs[c + 1];
                } else if (MODE == 4) {
                    float rs = g.rowscal[(size_t)tk[r] * Fn + z];
                    float2 mv = *reinterpret_cast<const float2*>(&mixp[off]);
                    v0 = rs * (v0 + mv.x);
                    v1 = rs * (v1 + mv.y);
                } else if (MODE == 6) {
                    float2 prev = *reinterpret_cast<const float2*>(&C[off]);
                    v0 += prev.x;
                    v1 += prev.y;
                }
                *reinterpret_cast<float2*>(&C[off]) = make_float2(v0, v1);
            }
        }
    }
}

// dual-GEMM kernel: linear grid; first nb1 blocks run GEMM1, rest run GEMM2.
template <int M1, int M2>
__global__ void __launch_bounds__(256, 2)
gemm_dual(GArgs g1, int gx1, int gy1, int nb1, GArgs g2, int gx2, int gy2) {
    int b = blockIdx.x;
    if (b < nb1) {
        int z = b / (gx1 * gy1);
        int rem = b % (gx1 * gy1);
        gemm_body<M1>(g1, rem % gx1, rem / gx1, z);
    } else {
        b -= nb1;
        int z = b / (gx2 * gy2);
        int rem = b % (gx2 * gy2);
        gemm_body<M2>(g2, rem % gx2, rem / gx2, z);
    }
}

// single-GEMM kernel
template <int MODE>
__global__ void __launch_bounds__(256, 2)
gemm_tn(GArgs g) {
    gemm_body<MODE>(g, blockIdx.x, blockIdx.y, blockIdx.z);
}

// ---------------- host ----------------
#define SYMP(v, T) ({ void* _p = nullptr; cudaGetSymbolAddress(&_p, v); (T*)_p; })

extern "C" void kernel_launch(void* const* d_in, const int* in_sizes, int n_in,
                              void* d_out, int out_size) {
    const float* x          = (const float*)d_in[0];
    const float* gate_wt    = (const float*)d_in[1];
    const int*   inv        = (const int*)d_in[2];
    const float* mask_up_W  = (const float*)d_in[3];
    const float* gate_W     = (const float*)d_in[4];
    const float* gate_qa    = (const float*)d_in[5];
    const float* gate_qb    = (const float*)d_in[6];
    const float* gate_scale = (const float*)d_in[7];
    const float* up_W       = (const float*)d_in[8];
    const float* up_qa      = (const float*)d_in[9];
    const float* up_qb      = (const float*)d_in[10];
    const float* up_scale   = (const float*)d_in[11];
    const float* down_W     = (const float*)d_in[12];
    const float* down_qa    = (const float*)d_in[13];
    const float* down_qb    = (const float*)d_in[14];
    const float* down_scale = (const float*)d_in[15];
    const float* sh_gate_W  = (const float*)d_in[16];
    const float* sh_up_W    = (const float*)d_in[17];
    const float* sh_down_W  = (const float*)d_in[18];
    float* out = (float*)d_out;

    float* p_soft  = SYMP(g_soft, float);
    float* p_scal  = SYMP(g_scalar, float);
    int*   p_cnt   = SYMP(g_cnt, int);
    int*   p_tok   = SYMP(g_tok, int);
    int*   p_pos   = SYMP(g_pos, int);
    float* p_xe    = SYMP(g_xe, float);
    float* p_gu    = SYMP(g_gu, float);
    float* p_mgu   = SYMP(g_mgu, float);
    float* p_hmid  = SYMP(g_hmid, float);
    float* p_md    = SYMP(g_md, float);
    float* p_mixd  = SYMP(g_mixd, float);
    float* p_down  = SYMP(g_down, float);
    float* p_qbtgu = SYMP(g_qbtgu, float);
    float* p_qbtd  = SYMP(g_qbtd, float);
    float* p_shgu  = SYMP(g_shgu, float);
    float* p_shm   = SYMP(g_shm, float);
    float* p_sgu   = SYMP(g_sgu, float);
    float* p_xr    = SYMP(g_xr, float);

    cudaFuncSetAttribute(gemm_dual<1, 0>, cudaFuncAttributeMaxDynamicSharedMemorySize, SMEM_BYTES);
    cudaFuncSetAttribute(gemm_dual<1, 0>, cudaFuncAttributePreferredSharedMemoryCarveout, 100);
    cudaFuncSetAttribute(gemm_dual<0, 2>, cudaFuncAttributeMaxDynamicSharedMemorySize, SMEM_BYTES);
    cudaFuncSetAttribute(gemm_dual<0, 2>, cudaFuncAttributePreferredSharedMemoryCarveout, 100);
    cudaFuncSetAttribute(gemm_dual<1, 6>, cudaFuncAttributeMaxDynamicSharedMemorySize, SMEM_BYTES);
    cudaFuncSetAttribute(gemm_dual<1, 6>, cudaFuncAttributePreferredSharedMemoryCarveout, 100);
    cudaFuncSetAttribute(gemm_dual<0, 4>, cudaFuncAttributeMaxDynamicSharedMemorySize, SMEM_BYTES);
    cudaFuncSetAttribute(gemm_dual<0, 4>, cudaFuncAttributePreferredSharedMemoryCarveout, 100);
    cudaFuncSetAttribute(gemm_tn<3>, cudaFuncAttributeMaxDynamicSharedMemorySize, SMEM_BYTES);
    cudaFuncSetAttribute(gemm_tn<3>, cudaFuncAttributePreferredSharedMemoryCarveout, 100);

#define NB(n) ((int)(((n) + 255) / 256))

    // 1. router (exact fp32)
    router_kernel<<<Tn, 128>>>(x, gate_wt, inv, p_soft, p_scal);
    // 2. deterministic token compaction
    compact_kernel<<<Fn, Tn>>>(p_scal, p_cnt, p_tok, p_pos);
    // 3. xe (compacted, rounded at producer)
    xe_kernel<<<NB((size_t)Fn * Tn * Hn), 256>>>(x, mask_up_W, p_soft, p_cnt, p_tok, p_xe);
    // 4. rounded x for shared path (independent)
    round_copy<<<NB((size_t)Tn * Hn / 4), 256>>>(
        (const float4*)x, (float4*)p_xr, (int)((size_t)Tn * Hn / 4));
    // 5-7. weight layout preps
    tq2_kernel<<<NB(Fn * IGU * 128), 256>>>(gate_qb, up_qb, p_qbtgu);
    tq_kernel<<<NB(Fn * Hn * KRn), 256>>>(down_qb, p_qbtd, Hn);
    sc2<<<NB(2 * Fn * In), 256>>>(gate_scale, up_scale, p_sgu);

    // arg structs
    GArgs aGU  = { p_xe, Hn, (size_t)Tn * Hn, gate_W, Hn, (size_t)In * Hn, up_W, In,
                   p_gu, IGU, (size_t)Tn * IGU, IGU, Hn,
                   nullptr, nullptr, nullptr, 0, nullptr, p_cnt, nullptr };
    GArgs aLA  = { p_xe, Hn, (size_t)Tn * Hn, gate_qa, Hn, (size_t)KRn * Hn, up_qa, KRn,
                   p_mgu, 128, (size_t)Tn * 128, 128, Hn,
                   p_soft, nullptr, nullptr, 0, nullptr, p_cnt, p_tok };
    GArgs aMIX = { p_mgu, 128, (size_t)Tn * 128, p_qbtgu, 128, (size_t)IGU * 128, p_qbtgu, IGU,
                   p_gu, IGU, (size_t)Tn * IGU, IGU, 128,
                   nullptr, nullptr, p_sgu, IGU, nullptr, p_cnt, nullptr };
    // shared gate||up split-K halves (K=1024 each)
    GArgs aSHGlo = { p_xr, Hn, 0, sh_gate_W, Hn, 0, sh_up_W, ISHn,
                     p_shgu, SH2, 0, SH2, 1024,
                     nullptr, nullptr, nullptr, 0, nullptr, nullptr, nullptr };
    GArgs aSHGhi = { p_xr + 1024, Hn, 0, sh_gate_W + 1024, Hn, 0, sh_up_W + 1024, ISHn,
                     p_shgu, SH2, 0, SH2, 1024,
                     nullptr, nullptr, nullptr, 0, nullptr, nullptr, nullptr };
    GArgs aDLA = { p_hmid, In, (size_t)Tn * In, down_qa, In, (size_t)KRn * In, down_qa, KRn,
                   p_md, KRn, (size_t)Tn * KRn, KRn, In,
                   p_soft, nullptr, nullptr, 0, nullptr, p_cnt, p_tok };
    GArgs aMXD = { p_md, KRn, (size_t)Tn * KRn, p_qbtd, KRn, (size_t)Hn * KRn, p_qbtd, Hn,
                   p_mixd, Hn, (size_t)Tn * Hn, Hn, KRn,
                   nullptr, nullptr, down_scale, Hn, nullptr, p_cnt, nullptr };
    GArgs aDWN = { p_hmid, In, (size_t)Tn * In, down_W, In, (size_t)Hn * In, down_W, Hn,
                   p_down, Hn, (size_t)Tn * Hn, Hn, In,
                   nullptr, p_scal, nullptr, 0, p_mixd, p_cnt, p_tok };
    GArgs aSHD = { p_shm, ISHn, 0, sh_down_W, ISHn, 0, sh_down_W, Hn,
                   out, Hn, 0, Hn, ISHn,
                   nullptr, nullptr, nullptr, 0, nullptr, nullptr, nullptr };

    // 8. DUAL: LoRA-a (64 first) + gate||up GEMM (1408) -- 5 perfect waves
    gemm_dual<1, 0><<<64 + 1408, 256, SMEM_BYTES>>>(aLA, 1, 8, 64, aGU, 22, 8);

    // 9. DUAL: SHG_lo (352, K=1024, first) + mix GEMM in-place (1408 light)
    gemm_dual<0, 2><<<352 + 1408, 256, SMEM_BYTES>>>(aSHGlo, 44, 8, 352, aMIX, 22, 8);

    // 10. hmid = silu(gate)*up
    fuse_kernel<<<NB((size_t)Fn * Tn * In), 256>>>(p_gu, p_cnt, p_hmid);

    // 11. DUAL: down LoRA-a (64 first) + SHG_hi (352, K=1024, MODE6 accumulate)
    gemm_dual<1, 6><<<64 + 352, 256, SMEM_BYTES>>>(aDLA, 1, 8, 64, aSHGhi, 44, 8);

    // 12. mixd (1024 light blocks)
    gemm_tn<3><<<dim3(16, 8, Fn), 256, SMEM_BYTES>>>(aMXD);
    // 13. swiglu (p_shgu complete after step 11)
    swiglu_kernel<<<NB((size_t)Tn * ISHn), 256>>>(p_shgu, p_shm);

    // 14. DUAL: shared down GEMM (128 first, heavy) + down GEMM MODE4 (1024)
    gemm_dual<0, 4><<<128 + 1024, 256, SMEM_BYTES>>>(aSHD, 16, 8, 128, aDWN, 16, 8);

    // 15. out += gathered expert outputs
    reduce_kernel<<<NB(Tn * Hn), 256>>>(out, p_down, p_pos);

#undef NB
    (void)in_sizes; (void)n_in; (void)out_size;
}